// round 2
// baseline (speedup 1.0000x reference)
#include <cuda_runtime.h>
#include <cstdint>

// ---------------------------------------------------------------------------
// CapsuleLayer fused dynamic routing, fp32, restructured:
//   K1: Wsum[n,o,i] = sum_d W[n,o,d,i]                       (4 MB)
//   K2: routing -> c2[o,n,b]  (softmax chain on h = Wsum.x)  (16 MB)
//   K3: s[b,o,d] = sum_{n,i} W[n,o,d,i] * c2[b,n,o] * x[b,n,i]; squash inline.
// K3 uses packed f32x2 FMAs (fma.rn.f32x2) with packed accumulators.
// ---------------------------------------------------------------------------

#define BATCH 64
#define NI    2048
#define DI    16
#define NO    32
#define DOUT  16

__device__ float g_wsum[NI * NO * DI];            // 4 MB  [n][o][i]
__device__ float g_c2[(size_t)NO * NI * BATCH];   // 16 MB [o][n][b]

// ---------------- packed f32x2 helpers -------------------------------------
__device__ __forceinline__ void ffma2(unsigned long long& d,
                                      unsigned long long a,
                                      unsigned long long b) {
    asm("fma.rn.f32x2 %0, %1, %2, %0;" : "+l"(d) : "l"(a), "l"(b));
}
__device__ __forceinline__ unsigned long long pack2(float a, float b) {
    unsigned long long r;
    asm("mov.b64 %0, {%1, %2};" : "=l"(r) : "f"(a), "f"(b));
    return r;
}
__device__ __forceinline__ float hadd2(unsigned long long v) {
    float lo, hi;
    asm("mov.b64 {%0, %1}, %2;" : "=f"(lo), "=f"(hi) : "l"(v));
    return lo + hi;
}

__device__ __forceinline__ unsigned smem_u32(const void* p) {
    return (unsigned)__cvta_generic_to_shared(p);
}
__device__ __forceinline__ void cp16(unsigned dst, const void* src) {
    asm volatile("cp.async.cg.shared.global [%0], [%1], 16;\n" :: "r"(dst), "l"(src));
}
__device__ __forceinline__ void cp_commit() {
    asm volatile("cp.async.commit_group;\n" ::: "memory");
}

// ============================================================================
// K1: Wsum[n][o][i] = sum_d W[n][o][d][i].  262144 threads, one float4 each.
// ============================================================================
__global__ void __launch_bounds__(256)
caps_wsum(const float* __restrict__ Wg) {
    int flat = blockIdx.x * 256 + threadIdx.x;      // (n*32 + o)*4 + iq
    int iq = flat & 3;
    int no = flat >> 2;                             // n*32 + o, 0..65535
    const float4* src = (const float4*)(Wg + (size_t)no * 256 + iq * 4);
    float4 s = make_float4(0.f, 0.f, 0.f, 0.f);
#pragma unroll
    for (int d = 0; d < 16; d++) {
        float4 v = __ldg(src + d * 4);              // stride 16 floats = 4 float4
        s.x += v.x; s.y += v.y; s.z += v.z; s.w += v.w;
    }
    *(float4*)(g_wsum + (size_t)no * 16 + iq * 4) = s;
}

// ============================================================================
// K2: routing.  grid (4 bs, 2048 n), 512 threads = 16 warps.
// Warp wid handles b = bs*16+wid; lane = o.  No-max softmax (args bounded).
// ============================================================================
__global__ void __launch_bounds__(512)
caps_route(const float* __restrict__ inp) {
    __shared__ float c2s[NO * 17];
    const int t    = threadIdx.x;
    const int lane = t & 31;         // o
    const int wid  = t >> 5;         // b within bs-group
    const int bs   = blockIdx.x;
    const int n    = blockIdx.y;
    const int b    = bs * 16 + wid;

    const float4* wr = (const float4*)(g_wsum + ((size_t)n * 32 + lane) * 16);
    const float4* xr = (const float4*)(inp + ((size_t)b * NI + n) * 16);
    float4 w0 = __ldg(wr + 0), w1 = __ldg(wr + 1), w2 = __ldg(wr + 2), w3 = __ldg(wr + 3);
    float4 x0 = __ldg(xr + 0), x1 = __ldg(xr + 1), x2 = __ldg(xr + 2), x3 = __ldg(xr + 3);

    float h = w0.x * x0.x;
    h = fmaf(w0.y, x0.y, h); h = fmaf(w0.z, x0.z, h); h = fmaf(w0.w, x0.w, h);
    h = fmaf(w1.x, x1.x, h); h = fmaf(w1.y, x1.y, h); h = fmaf(w1.z, x1.z, h); h = fmaf(w1.w, x1.w, h);
    h = fmaf(w2.x, x2.x, h); h = fmaf(w2.y, x2.y, h); h = fmaf(w2.z, x2.z, h); h = fmaf(w2.w, x2.w, h);
    h = fmaf(w3.x, x3.x, h); h = fmaf(w3.y, x3.y, h); h = fmaf(w3.z, x3.z, h); h = fmaf(w3.w, x3.w, h);

    float b1 = h * 0.03125f;                   // b after iter 0 = h/32
    float e1 = __expf(b1);
    float s1 = e1;
#pragma unroll
    for (int s = 16; s > 0; s >>= 1) s1 += __shfl_xor_sync(0xffffffffu, s1, s);
    float c1 = __fdividef(e1, s1);
    float b2 = fmaf(c1, h, b1);                // b after iter 1
    float e2 = __expf(b2);
    float s2 = e2;
#pragma unroll
    for (int s = 16; s > 0; s >>= 1) s2 += __shfl_xor_sync(0xffffffffu, s2, s);
    float c2 = __fdividef(e2, s2);

    c2s[lane * 17 + wid] = c2;                 // transpose for coalesced store
    __syncthreads();
    const int o2  = t >> 4;
    const int b16 = t & 15;
    g_c2[((size_t)o2 * NI + n) * BATCH + bs * 16 + b16] = c2s[o2 * 17 + b16];
}

// ============================================================================
// K3: main contraction + squash.  grid (4 bs, 32 o), 512 threads, 1 wave.
// Per chunk of 32 n: stage W (cp.async, double-buffered) + ys = c2*x (smem),
// then per-thread (b, 4d, n-split) packed-FMA accumulation.
// ============================================================================
#define CHUNK    32
#define NCHUNKS  (NI / CHUNK)                  // 64
#define WBUF_U64 (CHUNK * 128)                 // 32 n * 256 floats = 4096 u64
#define YS_BSTR  9                             // f32x2 per b-row (8 + 1 pad)
#define YS_NSTR  (16 * YS_BSTR)               // 144 u64 per n
#define YS_U64   (CHUNK * YS_NSTR)            // 4608 u64 = 36864 B
#define SMEM3_BYTES (2 * WBUF_U64 * 8 + YS_U64 * 8)   // 65536 + 36864 = 102400

__global__ void __launch_bounds__(512, 1)
caps_contract(const float* __restrict__ inp, const float* __restrict__ Wg,
              float* __restrict__ out) {
    extern __shared__ unsigned long long sm[];
    unsigned long long* Wsm = sm;                       // 2 * 4096 u64
    unsigned long long* ysu = sm + 2 * WBUF_U64;        // 4608 u64

    const int t  = threadIdx.x;
    const int bs = blockIdx.x;       // 0..3
    const int o  = blockIdx.y;       // 0..31

    // stage mapping: (nn, bS) ; main mapping: (b, dg, ns)
    const int nnS = t >> 4;          // 0..31
    const int bS  = t & 15;
    const int b   = t & 15;
    const int dg  = (t >> 4) & 3;
    const int ns  = t >> 6;          // 0..7  (4 n each)

    const float* Wbase = Wg + (size_t)o * 256;                    // + n*8192
    const float* xbase = inp + ((size_t)(bs * 16 + bS) * NI) * 16;
    const float* cbase = g_c2 + ((size_t)o * NI) * BATCH + bs * 16 + bS;

    // ---- prefetch chunk 0: W via cp.async, x/c2 via regs --------------------
    {
        const float* Wc = Wbase;     // n0 = 0
#pragma unroll
        for (int k = 0; k < 4; k++) {
            int c  = t + k * 512;                 // 0..2047 16B-chunks
            int nn = c >> 6;
            int j  = (c & 63) << 2;
            cp16(smem_u32((float*)Wsm + nn * 256 + j), Wc + (size_t)nn * 8192 + j);
        }
        cp_commit();
    }
    float4 xA0, xA1, xA2, xA3;
    float  cA;
    {
        const float4* xr = (const float4*)(xbase + (size_t)nnS * 16);
        xA0 = __ldg(xr + 0); xA1 = __ldg(xr + 1); xA2 = __ldg(xr + 2); xA3 = __ldg(xr + 3);
        cA  = __ldg(cbase + (size_t)nnS * BATCH);
    }

    unsigned long long acc0 = 0, acc1 = 0, acc2r = 0, acc3 = 0;

    for (int chunk = 0; chunk < NCHUNKS; chunk++) {
        const int cur = chunk & 1;
        if (chunk + 1 < NCHUNKS) {
            const float* Wc = Wbase + (size_t)(chunk + 1) * CHUNK * 8192;
            unsigned long long* wdst = Wsm + (cur ^ 1) * WBUF_U64;
#pragma unroll
            for (int k = 0; k < 4; k++) {
                int c  = t + k * 512;
                int nn = c >> 6;
                int j  = (c & 63) << 2;
                cp16(smem_u32((float*)wdst + nn * 256 + j), Wc + (size_t)nn * 8192 + j);
            }
            cp_commit();
            asm volatile("cp.async.wait_group 1;\n" ::: "memory");
        } else {
            asm volatile("cp.async.wait_group 0;\n" ::: "memory");
        }
        __syncthreads();   // W[cur] visible everywhere; prev-iter ys reads done

        // ---- stage ys[nn][b] = c2 * x ------------------------------------
        {
            unsigned long long* yrow = ysu + nnS * YS_NSTR + bS * YS_BSTR;
            yrow[0] = pack2(cA * xA0.x, cA * xA0.y);
            yrow[1] = pack2(cA * xA0.z, cA * xA0.w);
            yrow[2] = pack2(cA * xA1.x, cA * xA1.y);
            yrow[3] = pack2(cA * xA1.z, cA * xA1.w);
            yrow[4] = pack2(cA * xA2.x, cA * xA2.y);
            yrow[5] = pack2(cA * xA2.z, cA * xA2.w);
            yrow[6] = pack2(cA * xA3.x, cA * xA3.y);
            yrow[7] = pack2(cA * xA3.z, cA * xA3.w);
        }
        // prefetch next chunk's x/c2 (overlaps with compute below)
        if (chunk + 1 < NCHUNKS) {
            size_t nglob = (size_t)(chunk + 1) * CHUNK + nnS;
            const float4* xr = (const float4*)(xbase + nglob * 16);
            xA0 = __ldg(xr + 0); xA1 = __ldg(xr + 1); xA2 = __ldg(xr + 2); xA3 = __ldg(xr + 3);
            cA  = __ldg(cbase + nglob * BATCH);
        }
        __syncthreads();   // ys ready

        // ---- main: 4 n per thread, 4 d, 8 packed-i FMAs each ---------------
        const unsigned long long* wb = Wsm + cur * WBUF_U64;
#pragma unroll
        for (int j = 0; j < 4; j++) {
            const int nn = ns * 4 + j;
            const unsigned long long* yp = ysu + nn * YS_NSTR + b * YS_BSTR;
            unsigned long long y0 = yp[0], y1 = yp[1], y2 = yp[2], y3 = yp[3];
            unsigned long long y4 = yp[4], y5 = yp[5], y6 = yp[6], y7 = yp[7];
            const ulonglong2* wrow =
                (const ulonglong2*)(wb + nn * 128 + dg * 32);   // d = dg*4.. , 8 u64/d
#pragma unroll
            for (int dd = 0; dd < 4; dd++) {
                ulonglong2 wA = wrow[dd * 4 + 0];
                ulonglong2 wB = wrow[dd * 4 + 1];
                ulonglong2 wC = wrow[dd * 4 + 2];
                ulonglong2 wD = wrow[dd * 4 + 3];
                unsigned long long* ap = (dd == 0) ? &acc0 : (dd == 1) ? &acc1
                                       : (dd == 2) ? &acc2r : &acc3;
                ffma2(*ap, wA.x, y0); ffma2(*ap, wA.y, y1);
                ffma2(*ap, wB.x, y2); ffma2(*ap, wB.y, y3);
                ffma2(*ap, wC.x, y4); ffma2(*ap, wC.y, y5);
                ffma2(*ap, wD.x, y6); ffma2(*ap, wD.y, y7);
            }
        }
    }

    // ---- epilogue: reduce over ns, squash over d, store --------------------
    __syncthreads();
    float* red = (float*)sm;                    // reuse smem
#pragma unroll
    for (int dd = 0; dd < 4; dd++) {
        unsigned long long a = (dd == 0) ? acc0 : (dd == 1) ? acc1
                             : (dd == 2) ? acc2r : acc3;
        red[ns * 256 + b * 16 + dg * 4 + dd] = hadd2(a);
    }
    __syncthreads();

    float* s_sm = red + 2048;
    float sval = 0.f;
    if (t < 256) {
        const int b2 = t >> 4;
        const int d2 = t & 15;
#pragma unroll
        for (int k = 0; k < 8; k++) sval += red[k * 256 + b2 * 16 + d2];
        s_sm[b2 * 16 + d2] = sval;
    }
    __syncthreads();
    if (t < 256) {
        const int b2 = t >> 4;
        const int d2 = t & 15;
        float s2 = 0.f;
#pragma unroll
        for (int k = 0; k < 16; k++) {
            float v = s_sm[b2 * 16 + k];
            s2 = fmaf(v, v, s2);
        }
        const float scale = s2 / ((1.f + s2) * sqrtf(s2 + 1e-7f));
        out[(size_t)(bs * 16 + b2) * 512 + o * 16 + d2] = scale * sval;
    }
}

// ============================================================================
extern "C" void kernel_launch(void* const* d_in, const int* in_sizes, int n_in,
                              void* d_out, int out_size) {
    const float* inp;
    const float* Wg;
    if (in_sizes[0] == BATCH * NI * DI) {
        inp = (const float*)d_in[0];
        Wg  = (const float*)d_in[1];
    } else {
        inp = (const float*)d_in[1];
        Wg  = (const float*)d_in[0];
    }

    cudaFuncSetAttribute(caps_contract, cudaFuncAttributeMaxDynamicSharedMemorySize,
                         SMEM3_BYTES);

    caps_wsum<<<1024, 256>>>(Wg);
    caps_route<<<dim3(4, NI), 512>>>(inp);
    caps_contract<<<dim3(4, NO), 512, SMEM3_BYTES>>>(inp, Wg, (float*)d_out);
}

// round 6
// speedup vs baseline: 1.0775x; 1.0775x over previous
#include <cuda_runtime.h>
#include <cstdint>

typedef unsigned long long ull;

#define BATCH 64
#define NI    2048
#define DI    16
#define NO    32
#define DOUT  16

__device__ float g_c2[(size_t)NO * NI * BATCH];   // 16 MB [o][n][b]
__device__ float g_part[4 * BATCH * 512];         // [kp][b][o*16+d]

// ---------------- packed f32x2 helpers -------------------------------------
__device__ __forceinline__ void ffma2(ull& d, ull a, ull b) {
    asm("fma.rn.f32x2 %0, %1, %2, %0;" : "+l"(d) : "l"(a), "l"(b));
}
__device__ __forceinline__ ull pack2(float a, float b) {
    ull r; asm("mov.b64 %0, {%1, %2};" : "=l"(r) : "f"(a), "f"(b)); return r;
}
__device__ __forceinline__ float hadd2(ull v) {
    float lo, hi; asm("mov.b64 {%0, %1}, %2;" : "=f"(lo), "=f"(hi) : "l"(v));
    return lo + hi;
}
__device__ __forceinline__ unsigned smem_u32(const void* p) {
    return (unsigned)__cvta_generic_to_shared(p);
}
__device__ __forceinline__ void cp16(unsigned dst, const void* src) {
    asm volatile("cp.async.cg.shared.global [%0], [%1], 16;\n" :: "r"(dst), "l"(src));
}
__device__ __forceinline__ void cp_commit() {
    asm volatile("cp.async.commit_group;\n" ::: "memory");
}

// ============================================================================
// K1: fused Wsum + routing.  One block per n (2048 blocks, 512 threads).
//   wsum[o][i] = sum_d W[n][o][d][i];  h[b][o] = x[b][n]·wsum[o]
//   2-step softmax chain -> c2 -> g_c2[o][n][b]
// ============================================================================
__global__ void __launch_bounds__(512)
caps_route(const float* __restrict__ inp, const float* __restrict__ Wg) {
    __shared__ float ws[512];        // [o*16 + i]
    __shared__ float hs[64 * 33];    // [b][o] pad 33
    __shared__ float c2s[32 * 65];   // [o][b] pad 65

    const int t = threadIdx.x;
    const int n = blockIdx.x;

    // --- phase A: wsum.  thread = (o = t>>4, i = t&15) ---
    {
        const float* wp = Wg + (size_t)n * 8192 + (t >> 4) * 256 + (t & 15);
        float s = 0.f;
#pragma unroll
        for (int d = 0; d < 16; d++) s += __ldg(wp + d * 16);
        ws[t] = s;
    }
    __syncthreads();

    // --- phase B: h[b][o].  thread = (b = t>>3, og = t&7), o = og + 8j ---
    {
        const int b  = t >> 3;
        const int og = t & 7;
        const float4* xr = (const float4*)(inp + ((size_t)b * NI + n) * 16);
        float4 x0 = __ldg(xr + 0), x1 = __ldg(xr + 1);
        float4 x2 = __ldg(xr + 2), x3 = __ldg(xr + 3);
#pragma unroll
        for (int j = 0; j < 4; j++) {
            const int o = og + 8 * j;
            const float4* wr = (const float4*)(ws + o * 16);
            float4 w0 = wr[0], w1 = wr[1], w2 = wr[2], w3 = wr[3];
            float h = w0.x * x0.x;
            h = fmaf(w0.y, x0.y, h); h = fmaf(w0.z, x0.z, h); h = fmaf(w0.w, x0.w, h);
            h = fmaf(w1.x, x1.x, h); h = fmaf(w1.y, x1.y, h); h = fmaf(w1.z, x1.z, h); h = fmaf(w1.w, x1.w, h);
            h = fmaf(w2.x, x2.x, h); h = fmaf(w2.y, x2.y, h); h = fmaf(w2.z, x2.z, h); h = fmaf(w2.w, x2.w, h);
            h = fmaf(w3.x, x3.x, h); h = fmaf(w3.y, x3.y, h); h = fmaf(w3.z, x3.z, h); h = fmaf(w3.w, x3.w, h);
            hs[b * 33 + o] = h;
        }
    }
    __syncthreads();

    // --- phase C: softmax chain. 16 warps x 4 b each; lane = o ---
    {
        const int wid  = t >> 5;
        const int lane = t & 31;
#pragma unroll
        for (int j = 0; j < 4; j++) {
            const int b = wid * 4 + j;
            float h  = hs[b * 33 + lane];
            float b1 = h * 0.03125f;
            float e1 = __expf(b1);
            float s1 = e1;
#pragma unroll
            for (int s = 16; s > 0; s >>= 1) s1 += __shfl_xor_sync(0xffffffffu, s1, s);
            float c1 = __fdividef(e1, s1);
            float b2 = fmaf(c1, h, b1);
            float e2 = __expf(b2);
            float s2 = e2;
#pragma unroll
            for (int s = 16; s > 0; s >>= 1) s2 += __shfl_xor_sync(0xffffffffu, s2, s);
            c2s[lane * 65 + b] = __fdividef(e2, s2);
        }
    }
    __syncthreads();

    // --- phase D: store c2 coalesced: thread (o = t>>4, bi = t&15) x 4 ---
    {
        const int o  = t >> 4;
        const int bi = t & 15;
        float* gp = g_c2 + ((size_t)o * NI + n) * BATCH;
#pragma unroll
        for (int k = 0; k < 4; k++) {
            const int b = bi + k * 16;
            gp[b] = c2s[o * 65 + b];
        }
    }
}

// ============================================================================
// K3: register-tiled contraction.  grid (4 kp, 32 o), 512 threads, 1 wave.
//   Thread tile: 8 b x 4 d, i-packed u64 accumulators.
//   Smem: W [buf][nn(8)][d(16):stride 10][ip(8)]  (1280 u64/buf, 16B-aligned rows)
//         Y [buf][nn(8)][ip(8):stride 80][bt(8):stride 10][bi(8)] (5120 u64/buf)
// ============================================================================
#define KP     4
#define NPB    (NI / KP)       // 512
#define CCH    8               // n per chunk
#define NCH    (NPB / CCH)     // 64
#define WDS    10              // u64 stride per d (80 B, keeps cp.async 16B-aligned)
#define WST    (CCH * 16 * WDS)  // 1280
#define YST    5120
#define SMEMC_BYTES ((2 * WST + 2 * YST) * 8)   // 102400

__global__ void __launch_bounds__(512, 1)
caps_contract(const float* __restrict__ inp, const float* __restrict__ Wg) {
    extern __shared__ ull sm[];
    ull* Wb = sm;               // 2 * WST
    ull* Yb = sm + 2 * WST;     // 2 * YST

    const int t  = threadIdx.x;
    const int kp = blockIdx.x;
    const int o  = blockIdx.y;

    // compute mapping
    const int ks  = t >> 5;            // 0..15 k-slice (warp id)
    const int tp  = t & 31;
    const int bt  = tp >> 2;           // 0..7  -> b = bt*8..
    const int dt  = tp & 3;            // 0..3  -> d = dt*4..
    const int nnK = ks >> 1;           // 0..7
    const int ipb = (ks & 1) * 4;      // 0 or 4

    // staging mapping
    const int sNN = t >> 6;            // 0..7
    const int sB  = t & 63;            // 0..63
    const int sBT = sB >> 3;
    const int sBI = sB & 7;
    // W cp mapping
    const int cNN = t >> 6;
    const int cc  = t & 63;
    const int cd  = cc >> 2;
    const int cq  = cc & 3;

    const float* Wbase = Wg + (size_t)o * 256 + (size_t)kp * NPB * 8192; // + n*8192
    const float* xbase = inp + ((size_t)sB * NI + kp * NPB) * 16;        // + n*16
    const float* cbase = g_c2 + ((size_t)o * NI + kp * NPB) * BATCH + sB;// + n*64

    // ---- prologue -----------------------------------------------------------
    {   // W chunk 0
        const float* src = Wbase + (size_t)cNN * 8192 + cd * 16 + cq * 4;
        cp16(smem_u32(Wb + cNN * (16 * WDS) + cd * WDS + cq * 2), src);
        cp_commit();
    }

    float4 x0, x1, x2, x3;  float cv;
    {   // x/c2 for chunk 0
        const float4* xr = (const float4*)(xbase + (size_t)sNN * 16);
        x0 = __ldg(xr + 0); x1 = __ldg(xr + 1); x2 = __ldg(xr + 2); x3 = __ldg(xr + 3);
        cv = __ldg(cbase + (size_t)sNN * BATCH);
    }
    {   // build Y[0]
        ull* yp = Yb + sNN * 640 + sBT * 10 + sBI;
        yp[0 * 80] = pack2(cv * x0.x, cv * x0.y);
        yp[1 * 80] = pack2(cv * x0.z, cv * x0.w);
        yp[2 * 80] = pack2(cv * x1.x, cv * x1.y);
        yp[3 * 80] = pack2(cv * x1.z, cv * x1.w);
        yp[4 * 80] = pack2(cv * x2.x, cv * x2.y);
        yp[5 * 80] = pack2(cv * x2.z, cv * x2.w);
        yp[6 * 80] = pack2(cv * x3.x, cv * x3.y);
        yp[7 * 80] = pack2(cv * x3.z, cv * x3.w);
    }
    {   // x/c2 for chunk 1
        const float4* xr = (const float4*)(xbase + (size_t)(CCH + sNN) * 16);
        x0 = __ldg(xr + 0); x1 = __ldg(xr + 1); x2 = __ldg(xr + 2); x3 = __ldg(xr + 3);
        cv = __ldg(cbase + (size_t)(CCH + sNN) * BATCH);
    }

    ull acc[8][4];
#pragma unroll
    for (int i = 0; i < 8; i++)
#pragma unroll
        for (int j = 0; j < 4; j++) acc[i][j] = 0ull;

    for (int c = 0; c < NCH; c++) {
        const int cur = c & 1;
        asm volatile("cp.async.wait_group 0;\n" ::: "memory");
        __syncthreads();          // W[cur] + Y[cur] ready; prev reads of Y[cur^1] done

        if (c + 1 < NCH) {
            // build Y[next] from regs (chunk c+1)
            ull* yp = Yb + (cur ^ 1) * YST + sNN * 640 + sBT * 10 + sBI;
            yp[0 * 80] = pack2(cv * x0.x, cv * x0.y);
            yp[1 * 80] = pack2(cv * x0.z, cv * x0.w);
            yp[2 * 80] = pack2(cv * x1.x, cv * x1.y);
            yp[3 * 80] = pack2(cv * x1.z, cv * x1.w);
            yp[4 * 80] = pack2(cv * x2.x, cv * x2.y);
            yp[5 * 80] = pack2(cv * x2.z, cv * x2.w);
            yp[6 * 80] = pack2(cv * x3.x, cv * x3.y);
            yp[7 * 80] = pack2(cv * x3.z, cv * x3.w);
            // stage W[next]
            const float* src = Wbase + (size_t)(c + 1) * CCH * 8192
                             + (size_t)cNN * 8192 + cd * 16 + cq * 4;
            cp16(smem_u32(Wb + (cur ^ 1) * WST + cNN * (16 * WDS) + cd * WDS + cq * 2), src);
            cp_commit();
            if (c + 2 < NCH) {   // prefetch x/c2 for chunk c+2
                const float4* xr = (const float4*)(xbase + (size_t)((c + 2) * CCH + sNN) * 16);
                x0 = __ldg(xr + 0); x1 = __ldg(xr + 1); x2 = __ldg(xr + 2); x3 = __ldg(xr + 3);
                cv = __ldg(cbase + (size_t)((c + 2) * CCH + sNN) * BATCH);
            }
        } else {
            cp_commit();          // keep wait_group balanced (empty group)
        }

        // ---- compute on cur: 4 ip-steps, 8b x 4d x 2i MACs each -------------
        const ull* Wc = Wb + cur * WST + nnK * (16 * WDS) + dt * (4 * WDS) + ipb;
        const ull* Yc = Yb + cur * YST + nnK * 640 + ipb * 80 + bt * 10;
#pragma unroll
        for (int ip4 = 0; ip4 < 4; ip4++) {
            const ull* yp = Yc + ip4 * 80;
            ulonglong2 ya  = *(const ulonglong2*)(yp + 0);
            ulonglong2 yb2 = *(const ulonglong2*)(yp + 2);
            ulonglong2 yc  = *(const ulonglong2*)(yp + 4);
            ulonglong2 yd  = *(const ulonglong2*)(yp + 6);
            const ull w0 = Wc[0 * WDS + ip4];
            const ull w1 = Wc[1 * WDS + ip4];
            const ull w2 = Wc[2 * WDS + ip4];
            const ull w3 = Wc[3 * WDS + ip4];
            ffma2(acc[0][0], w0, ya.x);  ffma2(acc[0][1], w1, ya.x);
            ffma2(acc[0][2], w2, ya.x);  ffma2(acc[0][3], w3, ya.x);
            ffma2(acc[1][0], w0, ya.y);  ffma2(acc[1][1], w1, ya.y);
            ffma2(acc[1][2], w2, ya.y);  ffma2(acc[1][3], w3, ya.y);
            ffma2(acc[2][0], w0, yb2.x); ffma2(acc[2][1], w1, yb2.x);
            ffma2(acc[2][2], w2, yb2.x); ffma2(acc[2][3], w3, yb2.x);
            ffma2(acc[3][0], w0, yb2.y); ffma2(acc[3][1], w1, yb2.y);
            ffma2(acc[3][2], w2, yb2.y); ffma2(acc[3][3], w3, yb2.y);
            ffma2(acc[4][0], w0, yc.x);  ffma2(acc[4][1], w1, yc.x);
            ffma2(acc[4][2], w2, yc.x);  ffma2(acc[4][3], w3, yc.x);
            ffma2(acc[5][0], w0, yc.y);  ffma2(acc[5][1], w1, yc.y);
            ffma2(acc[5][2], w2, yc.y);  ffma2(acc[5][3], w3, yc.y);
            ffma2(acc[6][0], w0, yd.x);  ffma2(acc[6][1], w1, yd.x);
            ffma2(acc[6][2], w2, yd.x);  ffma2(acc[6][3], w3, yd.x);
            ffma2(acc[7][0], w0, yd.y);  ffma2(acc[7][1], w1, yd.y);
            ffma2(acc[7][2], w2, yd.y);  ffma2(acc[7][3], w3, yd.y);
        }
    }

    // ---- epilogue: reduce over 16 k-slices, write partials ------------------
    __syncthreads();
    float* sred = (float*)Yb;    // 16 * 1025 floats fits in Y region (81920 B)
#pragma unroll
    for (int bb = 0; bb < 8; bb++)
#pragma unroll
        for (int j = 0; j < 4; j++)
            sred[ks * 1025 + (bt * 8 + bb) * 16 + dt * 4 + j] = hadd2(acc[bb][j]);
    __syncthreads();

#pragma unroll
    for (int rep = 0; rep < 2; rep++) {
        const int v = t + rep * 512;           // (b, d) flat
        float s = 0.f;
#pragma unroll
        for (int k = 0; k < 16; k++) s += sred[k * 1025 + v];
        const int b = v >> 4;
        const int d = v & 15;
        g_part[(kp * BATCH + b) * 512 + o * 16 + d] = s;
    }
}

// ============================================================================
// Finalize: sum 4 kp partials + squash.  grid 64 (b), 512 threads (o*16+d).
// ============================================================================
__global__ void __launch_bounds__(512)
caps_fin(float* __restrict__ out) {
    __shared__ float q[512];
    const int b  = blockIdx.x;
    const int od = threadIdx.x;
    float s = 0.f;
#pragma unroll
    for (int kp = 0; kp < 4; kp++) s += g_part[(kp * BATCH + b) * 512 + od];
    q[od] = s * s;
    __syncthreads();
    const int o = od >> 4;
    float s2 = 0.f;
#pragma unroll
    for (int k = 0; k < 16; k++) s2 += q[o * 16 + k];
    const float scale = s2 / ((1.f + s2) * sqrtf(s2 + 1e-7f));
    out[(size_t)b * 512 + od] = scale * s;
}

// ============================================================================
extern "C" void kernel_launch(void* const* d_in, const int* in_sizes, int n_in,
                              void* d_out, int out_size) {
    const float* inp;
    const float* Wg;
    if (in_sizes[0] == BATCH * NI * DI) {
        inp = (const float*)d_in[0];
        Wg  = (const float*)d_in[1];
    } else {
        inp = (const float*)d_in[1];
        Wg  = (const float*)d_in[0];
    }

    cudaFuncSetAttribute(caps_contract, cudaFuncAttributeMaxDynamicSharedMemorySize,
                         SMEMC_BYTES);

    caps_route<<<NI, 512>>>(inp, Wg);
    caps_contract<<<dim3(KP, NO), 512, SMEMC_BYTES>>>(inp, Wg);
    caps_fin<<<BATCH, 512>>>((float*)d_out);
}

// round 7
// speedup vs baseline: 1.3497x; 1.2526x over previous
#include <cuda_runtime.h>
#include <cstdint>

typedef unsigned long long ull;

#define BATCH 64
#define NI    2048
#define DI    16
#define NO    32
#define DOUT  16

__device__ float g_c2[(size_t)NO * NI * BATCH];   // 16 MB [o][n][b]
__device__ float g_part[4 * BATCH * 512];         // [kp][b][o*16+d]

// ---------------- packed f32x2 helpers -------------------------------------
__device__ __forceinline__ void ffma2(ull& d, ull a, ull b) {
    asm("fma.rn.f32x2 %0, %1, %2, %0;" : "+l"(d) : "l"(a), "l"(b));
}
__device__ __forceinline__ ull pack2(float a, float b) {
    ull r; asm("mov.b64 %0, {%1, %2};" : "=l"(r) : "f"(a), "f"(b)); return r;
}
__device__ __forceinline__ float hadd2(ull v) {
    float lo, hi; asm("mov.b64 {%0, %1}, %2;" : "=f"(lo), "=f"(hi) : "l"(v));
    return lo + hi;
}
__device__ __forceinline__ unsigned smem_u32(const void* p) {
    return (unsigned)__cvta_generic_to_shared(p);
}
__device__ __forceinline__ void cp16(unsigned dst, const void* src) {
    asm volatile("cp.async.cg.shared.global [%0], [%1], 16;\n" :: "r"(dst), "l"(src));
}
__device__ __forceinline__ void cp_commit() {
    asm volatile("cp.async.commit_group;\n" ::: "memory");
}

// ============================================================================
// K1: fused Wsum + routing.  One block per n (2048 blocks, 512 threads).
//   Phase A vectorized (LDG.128) with dh-split + smem reduce.
//   ws padded to stride 68 floats -> conflict-free phase-B reads.
// ============================================================================
__global__ void __launch_bounds__(512)
caps_route(const float* __restrict__ inp, const float* __restrict__ Wg) {
    __shared__ float4 psum[512];       // [o(32)][iq(4)][dh(4)]
    __shared__ float  ws[32 * 68];     // [o][i] stride 68
    __shared__ float  hs[64 * 33];     // [b][o]
    __shared__ float  c2s[32 * 65];    // [o][b]

    const int t = threadIdx.x;
    const int n = blockIdx.x;

    // --- phase A: partial wsum. thread = (o = t>>4, iq = (t>>2)&3, dh = t&3) ---
    {
        const int o  = t >> 4;
        const int iq = (t >> 2) & 3;
        const int dh = t & 3;
        const float4* wp = (const float4*)(Wg + (size_t)n * 8192 + o * 256 + dh * 64 + iq * 4);
        float4 s = make_float4(0.f, 0.f, 0.f, 0.f);
#pragma unroll
        for (int dd = 0; dd < 4; dd++) {
            float4 v = __ldg(wp + dd * 4);    // +dd*16 floats
            s.x += v.x; s.y += v.y; s.z += v.z; s.w += v.w;
        }
        psum[t] = s;
    }
    __syncthreads();

    // --- phase A': reduce over dh (threads 0..127) ---
    if (t < 128) {
        const int o  = t >> 2;
        const int iq = t & 3;
        const float4* p = psum + o * 16 + iq * 4;
        float4 a = p[0], b4 = p[1], c4 = p[2], d4 = p[3];
        float4 s = make_float4(a.x + b4.x + c4.x + d4.x,
                               a.y + b4.y + c4.y + d4.y,
                               a.z + b4.z + c4.z + d4.z,
                               a.w + b4.w + c4.w + d4.w);
        *(float4*)(ws + o * 68 + iq * 4) = s;
    }
    __syncthreads();

    // --- phase B: h[b][o].  thread = (b = t>>3, og = t&7), o = og + 8j ---
    {
        const int b  = t >> 3;
        const int og = t & 7;
        const float4* xr = (const float4*)(inp + ((size_t)b * NI + n) * 16);
        float4 x0 = __ldg(xr + 0), x1 = __ldg(xr + 1);
        float4 x2 = __ldg(xr + 2), x3 = __ldg(xr + 3);
#pragma unroll
        for (int j = 0; j < 4; j++) {
            const int o = og + 8 * j;
            const float4* wr = (const float4*)(ws + o * 68);
            float4 w0 = wr[0], w1 = wr[1], w2 = wr[2], w3 = wr[3];
            float h = w0.x * x0.x;
            h = fmaf(w0.y, x0.y, h); h = fmaf(w0.z, x0.z, h); h = fmaf(w0.w, x0.w, h);
            h = fmaf(w1.x, x1.x, h); h = fmaf(w1.y, x1.y, h); h = fmaf(w1.z, x1.z, h); h = fmaf(w1.w, x1.w, h);
            h = fmaf(w2.x, x2.x, h); h = fmaf(w2.y, x2.y, h); h = fmaf(w2.z, x2.z, h); h = fmaf(w2.w, x2.w, h);
            h = fmaf(w3.x, x3.x, h); h = fmaf(w3.y, x3.y, h); h = fmaf(w3.z, x3.z, h); h = fmaf(w3.w, x3.w, h);
            hs[b * 33 + o] = h;
        }
    }
    __syncthreads();

    // --- phase C: softmax chain. 16 warps x 4 b each; lane = o ---
    {
        const int wid  = t >> 5;
        const int lane = t & 31;
#pragma unroll
        for (int j = 0; j < 4; j++) {
            const int b = wid * 4 + j;
            float h  = hs[b * 33 + lane];
            float b1 = h * 0.03125f;
            float e1 = __expf(b1);
            float s1 = e1;
#pragma unroll
            for (int s = 16; s > 0; s >>= 1) s1 += __shfl_xor_sync(0xffffffffu, s1, s);
            float c1 = __fdividef(e1, s1);
            float b2 = fmaf(c1, h, b1);
            float e2 = __expf(b2);
            float s2 = e2;
#pragma unroll
            for (int s = 16; s > 0; s >>= 1) s2 += __shfl_xor_sync(0xffffffffu, s2, s);
            c2s[lane * 65 + b] = __fdividef(e2, s2);
        }
    }
    __syncthreads();

    // --- phase D: store c2 coalesced ---
    {
        const int o  = t >> 4;
        const int bi = t & 15;
        float* gp = g_c2 + ((size_t)o * NI + n) * BATCH;
#pragma unroll
        for (int k = 0; k < 4; k++) {
            const int b = bi + k * 16;
            gp[b] = c2s[o * 65 + b];
        }
    }
}

// ============================================================================
// K3: register-tiled contraction.  grid (4 kp, 32 o), 512 threads, 1 wave.
//   Warp w: nn = w&7, bh = w>>3.  Lane: bt = lane>>2, dt = lane&3.
//   Thread tile: 4 b (bh*32+bt*4+bb) x 4 d (dd*4+dt), packed-i u64 acc = 32 regs.
//   Smem: W [buf][nn(8)][d(16):stride 10][ip(8)]   (1280 u64/buf)
//         Y [buf][nn(8)][ip(8):stride 66][b(64)]   (4224 u64/buf)
// ============================================================================
#define KP     4
#define NPB    (NI / KP)         // 512
#define CCH    8                 // n per chunk
#define NCH    (NPB / CCH)       // 64
#define WDS    10                // u64 per d (80 B; cp.async dst stays 16B-aligned)
#define WST    (CCH * 16 * WDS)  // 1280
#define YIS    66                // u64 per (nn,ip) row (64 b + 2 pad; 528 B, 16B mult)
#define YST    (CCH * 8 * YIS)   // 4224
#define SMEMC_BYTES ((2 * WST + 2 * YST) * 8)   // 88064

__global__ void __launch_bounds__(512, 1)
caps_contract(const float* __restrict__ inp, const float* __restrict__ Wg) {
    extern __shared__ ull sm[];
    ull* Wb = sm;               // 2 * WST
    ull* Yb = sm + 2 * WST;     // 2 * YST

    const int t  = threadIdx.x;
    const int kp = blockIdx.x;
    const int o  = blockIdx.y;

    // compute mapping
    const int w    = t >> 5;
    const int lane = t & 31;
    const int nn   = w & 7;            // n within chunk
    const int bh   = w >> 3;           // b half (0/1)
    const int bt   = lane >> 2;        // 0..7 -> b = bh*32 + bt*4 + bb
    const int dt   = lane & 3;         // 0..3 -> d = dd*4 + dt

    // staging mapping (Y build)
    const int sNN = t >> 6;            // 0..7
    const int sB  = t & 63;            // 0..63
    // W cp mapping
    const int cNN = t >> 6;
    const int cc  = t & 63;
    const int cd  = cc >> 2;           // d 0..15
    const int cq  = cc & 3;            // i quad

    const float* Wbase = Wg + (size_t)o * 256 + (size_t)kp * NPB * 8192;
    const float* xbase = inp + ((size_t)sB * NI + kp * NPB) * 16;
    const float* cbase = g_c2 + ((size_t)o * NI + kp * NPB) * BATCH + sB;

    // ---- prologue ----------------------------------------------------------
    {   // W chunk 0 via cp.async
        const float* src = Wbase + (size_t)cNN * 8192 + cd * 16 + cq * 4;
        cp16(smem_u32(Wb + cNN * (16 * WDS) + cd * WDS + cq * 2), src);
        cp_commit();
    }
    float4 x0, x1, x2, x3;  float cv;
    {   // x/c2 for chunk 0
        const float4* xr = (const float4*)(xbase + (size_t)sNN * 16);
        x0 = __ldg(xr + 0); x1 = __ldg(xr + 1); x2 = __ldg(xr + 2); x3 = __ldg(xr + 3);
        cv = __ldg(cbase + (size_t)sNN * BATCH);
    }
    {   // build Y[0]: Y[sNN][ip][sB]
        ull* yp = Yb + sNN * (8 * YIS) + sB;
        yp[0 * YIS] = pack2(cv * x0.x, cv * x0.y);
        yp[1 * YIS] = pack2(cv * x0.z, cv * x0.w);
        yp[2 * YIS] = pack2(cv * x1.x, cv * x1.y);
        yp[3 * YIS] = pack2(cv * x1.z, cv * x1.w);
        yp[4 * YIS] = pack2(cv * x2.x, cv * x2.y);
        yp[5 * YIS] = pack2(cv * x2.z, cv * x2.w);
        yp[6 * YIS] = pack2(cv * x3.x, cv * x3.y);
        yp[7 * YIS] = pack2(cv * x3.z, cv * x3.w);
    }
    {   // x/c2 for chunk 1
        const float4* xr = (const float4*)(xbase + (size_t)(CCH + sNN) * 16);
        x0 = __ldg(xr + 0); x1 = __ldg(xr + 1); x2 = __ldg(xr + 2); x3 = __ldg(xr + 3);
        cv = __ldg(cbase + (size_t)(CCH + sNN) * BATCH);
    }

    ull acc[4][4];   // [bb][dd]
#pragma unroll
    for (int i = 0; i < 4; i++)
#pragma unroll
        for (int j = 0; j < 4; j++) acc[i][j] = 0ull;

    for (int c = 0; c < NCH; c++) {
        const int cur = c & 1;
        asm volatile("cp.async.wait_group 0;\n" ::: "memory");
        __syncthreads();          // buf[cur] ready; prev reads of buf[cur^1] done

        if (c + 1 < NCH) {
            // build Y[next] (chunk c+1) from regs
            ull* yp = Yb + (cur ^ 1) * YST + sNN * (8 * YIS) + sB;
            yp[0 * YIS] = pack2(cv * x0.x, cv * x0.y);
            yp[1 * YIS] = pack2(cv * x0.z, cv * x0.w);
            yp[2 * YIS] = pack2(cv * x1.x, cv * x1.y);
            yp[3 * YIS] = pack2(cv * x1.z, cv * x1.w);
            yp[4 * YIS] = pack2(cv * x2.x, cv * x2.y);
            yp[5 * YIS] = pack2(cv * x2.z, cv * x2.w);
            yp[6 * YIS] = pack2(cv * x3.x, cv * x3.y);
            yp[7 * YIS] = pack2(cv * x3.z, cv * x3.w);
            // stage W[next]
            const float* src = Wbase + (size_t)(c + 1) * CCH * 8192
                             + (size_t)cNN * 8192 + cd * 16 + cq * 4;
            cp16(smem_u32(Wb + (cur ^ 1) * WST + cNN * (16 * WDS) + cd * WDS + cq * 2), src);
            cp_commit();
            if (c + 2 < NCH) {   // prefetch x/c2 for chunk c+2
                const float4* xr = (const float4*)(xbase + (size_t)((c + 2) * CCH + sNN) * 16);
                x0 = __ldg(xr + 0); x1 = __ldg(xr + 1); x2 = __ldg(xr + 2); x3 = __ldg(xr + 3);
                cv = __ldg(cbase + (size_t)((c + 2) * CCH + sNN) * BATCH);
            }
        } else {
            cp_commit();          // keep wait_group balanced
        }

        // ---- compute on cur: 4 ip-pairs, 4b x 4d x 4i(packed 2x2) ----------
        const ull* WcB = Wb + cur * WST + nn * (16 * WDS) + dt * WDS;     // + dd*4*WDS + ipp*2
        const ull* YcB = Yb + cur * YST + nn * (8 * YIS) + bh * 32 + bt * 4; // + ip*YIS
#pragma unroll
        for (int ipp = 0; ipp < 4; ipp++) {
            ulonglong2 w0 = *(const ulonglong2*)(WcB + 0 * (4 * WDS) + ipp * 2);
            ulonglong2 w1 = *(const ulonglong2*)(WcB + 1 * (4 * WDS) + ipp * 2);
            ulonglong2 w2 = *(const ulonglong2*)(WcB + 2 * (4 * WDS) + ipp * 2);
            ulonglong2 w3 = *(const ulonglong2*)(WcB + 3 * (4 * WDS) + ipp * 2);
            const ull* ypa = YcB + (2 * ipp) * YIS;
            const ull* ypb = YcB + (2 * ipp + 1) * YIS;
            ulonglong2 ya0 = *(const ulonglong2*)(ypa);       // b0,b1 (ip even)
            ulonglong2 ya1 = *(const ulonglong2*)(ypa + 2);   // b2,b3
            ulonglong2 yb0 = *(const ulonglong2*)(ypb);       // (ip odd)
            ulonglong2 yb1 = *(const ulonglong2*)(ypb + 2);
            // ip even: w*.x
            ffma2(acc[0][0], w0.x, ya0.x); ffma2(acc[0][1], w1.x, ya0.x);
            ffma2(acc[0][2], w2.x, ya0.x); ffma2(acc[0][3], w3.x, ya0.x);
            ffma2(acc[1][0], w0.x, ya0.y); ffma2(acc[1][1], w1.x, ya0.y);
            ffma2(acc[1][2], w2.x, ya0.y); ffma2(acc[1][3], w3.x, ya0.y);
            ffma2(acc[2][0], w0.x, ya1.x); ffma2(acc[2][1], w1.x, ya1.x);
            ffma2(acc[2][2], w2.x, ya1.x); ffma2(acc[2][3], w3.x, ya1.x);
            ffma2(acc[3][0], w0.x, ya1.y); ffma2(acc[3][1], w1.x, ya1.y);
            ffma2(acc[3][2], w2.x, ya1.y); ffma2(acc[3][3], w3.x, ya1.y);
            // ip odd: w*.y
            ffma2(acc[0][0], w0.y, yb0.x); ffma2(acc[0][1], w1.y, yb0.x);
            ffma2(acc[0][2], w2.y, yb0.x); ffma2(acc[0][3], w3.y, yb0.x);
            ffma2(acc[1][0], w0.y, yb0.y); ffma2(acc[1][1], w1.y, yb0.y);
            ffma2(acc[1][2], w2.y, yb0.y); ffma2(acc[1][3], w3.y, yb0.y);
            ffma2(acc[2][0], w0.y, yb1.x); ffma2(acc[2][1], w1.y, yb1.x);
            ffma2(acc[2][2], w2.y, yb1.x); ffma2(acc[2][3], w3.y, yb1.x);
            ffma2(acc[3][0], w0.y, yb1.y); ffma2(acc[3][1], w1.y, yb1.y);
            ffma2(acc[3][2], w2.y, yb1.y); ffma2(acc[3][3], w3.y, yb1.y);
        }
    }

    // ---- epilogue: reduce over 8 nn-slices, write partials -----------------
    __syncthreads();
    float* sred = (float*)Yb;    // [nn(8)][b(64)][d(16)] = 8192 floats = 32 KB
    {
        const int b0 = bh * 32 + bt * 4;
#pragma unroll
        for (int bb = 0; bb < 4; bb++)
#pragma unroll
            for (int dd = 0; dd < 4; dd++)
                sred[nn * 1024 + (b0 + bb) * 16 + dd * 4 + dt] = hadd2(acc[bb][dd]);
    }
    __syncthreads();

#pragma unroll
    for (int rep = 0; rep < 2; rep++) {
        const int v = t + rep * 512;           // (b,d) flat
        float s = 0.f;
#pragma unroll
        for (int k = 0; k < 8; k++) s += sred[k * 1024 + v];
        const int b = v >> 4;
        const int d = v & 15;
        g_part[(kp * BATCH + b) * 512 + o * 16 + d] = s;
    }
}

// ============================================================================
// Finalize: sum 4 kp partials + squash.  grid 64 (b), 512 threads (o*16+d).
// ============================================================================
__global__ void __launch_bounds__(512)
caps_fin(float* __restrict__ out) {
    __shared__ float q[512];
    const int b  = blockIdx.x;
    const int od = threadIdx.x;
    float s = 0.f;
#pragma unroll
    for (int kp = 0; kp < 4; kp++) s += g_part[(kp * BATCH + b) * 512 + od];
    q[od] = s * s;
    __syncthreads();
    const int o = od >> 4;
    float s2 = 0.f;
#pragma unroll
    for (int k = 0; k < 16; k++) s2 += q[o * 16 + k];
    const float scale = s2 / ((1.f + s2) * sqrtf(s2 + 1e-7f));
    out[(size_t)b * 512 + od] = scale * s;
}

// ============================================================================
extern "C" void kernel_launch(void* const* d_in, const int* in_sizes, int n_in,
                              void* d_out, int out_size) {
    const float* inp;
    const float* Wg;
    if (in_sizes[0] == BATCH * NI * DI) {
        inp = (const float*)d_in[0];
        Wg  = (const float*)d_in[1];
    } else {
        inp = (const float*)d_in[1];
        Wg  = (const float*)d_in[0];
    }

    cudaFuncSetAttribute(caps_contract, cudaFuncAttributeMaxDynamicSharedMemorySize,
                         SMEMC_BYTES);

    caps_route<<<NI, 512>>>(inp, Wg);
    caps_contract<<<dim3(KP, NO), 512, SMEMC_BYTES>>>(inp, Wg);
    caps_fin<<<BATCH, 512>>>((float*)d_out);
}

// round 9
// speedup vs baseline: 3.0023x; 2.2243x over previous
#include <cuda_runtime.h>
#include <cstdint>

#define BATCH 64
#define NI    2048
#define DI    16
#define NO    32
#define DOUT  16

#define KP    4
#define NPB   (NI / KP)     // 512 n per block
#define NPW   (NPB / 16)    // 32 n per warp

__device__ float g_c2[(size_t)NO * NI * BATCH];   // [o][n][b]
__device__ float g_part[KP * BATCH * 512];        // [kp][b][o*16+d]

// ---------------------------------------------------------------------------
__device__ __forceinline__ float tf32r(float v) {
    unsigned r; asm("cvt.rna.tf32.f32 %0, %1;" : "=r"(r) : "f"(v));
    return __uint_as_float(r);
}
__device__ __forceinline__ void mma8(float* d,
                                     float a0, float a1, float a2, float a3,
                                     float b0, float b1) {
    asm volatile(
        "mma.sync.aligned.m16n8k8.row.col.f32.tf32.tf32.f32 "
        "{%0,%1,%2,%3}, {%4,%5,%6,%7}, {%8,%9}, {%0,%1,%2,%3};"
        : "+f"(d[0]), "+f"(d[1]), "+f"(d[2]), "+f"(d[3])
        : "r"(__float_as_uint(a0)), "r"(__float_as_uint(a1)),
          "r"(__float_as_uint(a2)), "r"(__float_as_uint(a3)),
          "r"(__float_as_uint(b0)), "r"(__float_as_uint(b1)));
}

// ============================================================================
// K1: fused Wsum + routing (unchanged from R7).
// ============================================================================
__global__ void __launch_bounds__(512)
caps_route(const float* __restrict__ inp, const float* __restrict__ Wg) {
    __shared__ float4 psum[512];
    __shared__ float  ws[32 * 68];
    __shared__ float  hs[64 * 33];
    __shared__ float  c2s[32 * 65];

    const int t = threadIdx.x;
    const int n = blockIdx.x;

    {
        const int o  = t >> 4;
        const int iq = (t >> 2) & 3;
        const int dh = t & 3;
        const float4* wp = (const float4*)(Wg + (size_t)n * 8192 + o * 256 + dh * 64 + iq * 4);
        float4 s = make_float4(0.f, 0.f, 0.f, 0.f);
#pragma unroll
        for (int dd = 0; dd < 4; dd++) {
            float4 v = __ldg(wp + dd * 4);
            s.x += v.x; s.y += v.y; s.z += v.z; s.w += v.w;
        }
        psum[t] = s;
    }
    __syncthreads();

    if (t < 128) {
        const int o  = t >> 2;
        const int iq = t & 3;
        const float4* p = psum + o * 16 + iq * 4;
        float4 a = p[0], b4 = p[1], c4 = p[2], d4 = p[3];
        float4 s = make_float4(a.x + b4.x + c4.x + d4.x, a.y + b4.y + c4.y + d4.y,
                               a.z + b4.z + c4.z + d4.z, a.w + b4.w + c4.w + d4.w);
        *(float4*)(ws + o * 68 + iq * 4) = s;
    }
    __syncthreads();

    {
        const int b  = t >> 3;
        const int og = t & 7;
        const float4* xr = (const float4*)(inp + ((size_t)b * NI + n) * 16);
        float4 x0 = __ldg(xr + 0), x1 = __ldg(xr + 1);
        float4 x2 = __ldg(xr + 2), x3 = __ldg(xr + 3);
#pragma unroll
        for (int j = 0; j < 4; j++) {
            const int o = og + 8 * j;
            const float4* wr = (const float4*)(ws + o * 68);
            float4 w0 = wr[0], w1 = wr[1], w2 = wr[2], w3 = wr[3];
            float h = w0.x * x0.x;
            h = fmaf(w0.y, x0.y, h); h = fmaf(w0.z, x0.z, h); h = fmaf(w0.w, x0.w, h);
            h = fmaf(w1.x, x1.x, h); h = fmaf(w1.y, x1.y, h); h = fmaf(w1.z, x1.z, h); h = fmaf(w1.w, x1.w, h);
            h = fmaf(w2.x, x2.x, h); h = fmaf(w2.y, x2.y, h); h = fmaf(w2.z, x2.z, h); h = fmaf(w2.w, x2.w, h);
            h = fmaf(w3.x, x3.x, h); h = fmaf(w3.y, x3.y, h); h = fmaf(w3.z, x3.z, h); h = fmaf(w3.w, x3.w, h);
            hs[b * 33 + o] = h;
        }
    }
    __syncthreads();

    {
        const int wid  = t >> 5;
        const int lane = t & 31;
#pragma unroll
        for (int j = 0; j < 4; j++) {
            const int b = wid * 4 + j;
            float h  = hs[b * 33 + lane];
            float b1 = h * 0.03125f;
            float e1 = __expf(b1);
            float s1 = e1;
#pragma unroll
            for (int s = 16; s > 0; s >>= 1) s1 += __shfl_xor_sync(0xffffffffu, s1, s);
            float c1 = __fdividef(e1, s1);
            float b2 = fmaf(c1, h, b1);
            float e2 = __expf(b2);
            float s2 = e2;
#pragma unroll
            for (int s = 16; s > 0; s >>= 1) s2 += __shfl_xor_sync(0xffffffffu, s2, s);
            c2s[lane * 65 + b] = __fdividef(e2, s2);
        }
    }
    __syncthreads();

    {
        const int o  = t >> 4;
        const int bi = t & 15;
        float* gp = g_c2 + ((size_t)o * NI + n) * BATCH;
#pragma unroll
        for (int k = 0; k < 4; k++) {
            const int b = bi + k * 16;
            gp[b] = c2s[o * 65 + b];
        }
    }
}

// ============================================================================
// K3: mma.sync tf32 contraction.  grid (4 kp, 32 o), 512 threads = 16 warps.
//   Warp w handles n = n0 + w + 16*j (j=0..31), full M=64 x N=16 output,
//   accumulating in 32 regs (4 mtiles x 2 dtiles x 4 c-regs).
//   3xTF32: d += aH*bH + aH*bL + aL*bH.
//   k-permutation: thread (c = lane&3) loads i = 4c..4c+3 (float4);
//   mma g in {0,1} uses elements {2g, 2g+1} as k-slots {c, c+4} on BOTH A and B.
// ============================================================================
#define SRED_STR 1032
#define SMEMC_BYTES (16 * SRED_STR * 4)   // 66048

__global__ __launch_bounds__(512, 1)
void caps_contract(const float* __restrict__ inp, const float* __restrict__ Wg) {
    extern __shared__ float sred[];
    const int t    = threadIdx.x;
    const int w    = t >> 5;
    const int lane = t & 31;
    const int r    = lane >> 2;    // fragment row-group 0..7
    const int c    = lane & 3;     // fragment k-group 0..3
    const int kp   = blockIdx.x;
    const int o    = blockIdx.y;
    const int n0   = kp * NPB;

    float acc[4][2][4];
#pragma unroll
    for (int mt = 0; mt < 4; mt++)
#pragma unroll
        for (int dt = 0; dt < 2; dt++)
#pragma unroll
            for (int q = 0; q < 4; q++) acc[mt][dt][q] = 0.f;

    // per-thread base pointers
    const float* xb  = inp + (size_t)r * (NI * DI) + 4 * c;       // + b_off*32768 + n*16
    const float* c2p = g_c2 + (size_t)o * (NI * BATCH) + r;       // + n*64 + b_off
    const float* wbp = Wg + (size_t)o * 256 + r * 16 + c * 4;     // + n*8192 + dt*128

    for (int j = 0; j < NPW; j++) {
        const int n = n0 + w + j * 16;

        // ---- B fragments: W[n][o][d][i], d = dt*8 + r, i = 4c..4c+3 --------
        float bh[2][2][2], bl[2][2][2];    // [dt][g][slot]
#pragma unroll
        for (int dt = 0; dt < 2; dt++) {
            float4 wv = __ldg((const float4*)(wbp + (size_t)n * 8192 + dt * 128));
            bh[dt][0][0] = tf32r(wv.x);  bl[dt][0][0] = wv.x - bh[dt][0][0];
            bh[dt][0][1] = tf32r(wv.y);  bl[dt][0][1] = wv.y - bh[dt][0][1];
            bh[dt][1][0] = tf32r(wv.z);  bl[dt][1][0] = wv.z - bh[dt][1][0];
            bh[dt][1][1] = tf32r(wv.w);  bl[dt][1][1] = wv.w - bh[dt][1][1];
        }

        const float* c2n = c2p + (size_t)n * BATCH;
        const float* xn  = xb + (size_t)n * DI;

#pragma unroll
        for (int mt = 0; mt < 4; mt++) {
            const float c2a = __ldg(c2n + mt * 16);          // b = mt*16 + r
            const float c2b = __ldg(c2n + mt * 16 + 8);      // b = mt*16 + 8 + r
            const float4 x0v = __ldg((const float4*)(xn + (size_t)(mt * 16) * (NI * DI)));
            const float4 x1v = __ldg((const float4*)(xn + (size_t)(mt * 16 + 8) * (NI * DI)));
            const float x0e[4] = {x0v.x, x0v.y, x0v.z, x0v.w};
            const float x1e[4] = {x1v.x, x1v.y, x1v.z, x1v.w};
#pragma unroll
            for (int g = 0; g < 2; g++) {
                const float y0 = c2a * x0e[2 * g];
                const float y2 = c2a * x0e[2 * g + 1];
                const float y1 = c2b * x1e[2 * g];
                const float y3 = c2b * x1e[2 * g + 1];
                const float aH0 = tf32r(y0), aH1 = tf32r(y1);
                const float aH2 = tf32r(y2), aH3 = tf32r(y3);
                const float aL0 = y0 - aH0, aL1 = y1 - aH1;
                const float aL2 = y2 - aH2, aL3 = y3 - aH3;
#pragma unroll
                for (int dt = 0; dt < 2; dt++) {
                    mma8(acc[mt][dt], aH0, aH1, aH2, aH3, bh[dt][g][0], bh[dt][g][1]);
                    mma8(acc[mt][dt], aH0, aH1, aH2, aH3, bl[dt][g][0], bl[dt][g][1]);
                    mma8(acc[mt][dt], aL0, aL1, aL2, aL3, bh[dt][g][0], bh[dt][g][1]);
                }
            }
        }
    }

    // ---- epilogue: per-warp partial -> smem, cross-warp reduce -------------
    // C fragment: c0 at (row=r, col=2c), c1 col+1, c2 row+8, c3 row+8 col+1.
#pragma unroll
    for (int mt = 0; mt < 4; mt++)
#pragma unroll
        for (int dt = 0; dt < 2; dt++) {
            const int base0 = w * SRED_STR + (mt * 16 + r) * 16 + dt * 8 + 2 * c;
            *(float2*)(sred + base0)       = make_float2(acc[mt][dt][0], acc[mt][dt][1]);
            *(float2*)(sred + base0 + 128) = make_float2(acc[mt][dt][2], acc[mt][dt][3]);
        }
    __syncthreads();

#pragma unroll
    for (int rep = 0; rep < 2; rep++) {
        const int v = t + rep * 512;          // (b, d) flat
        float s = 0.f;
#pragma unroll
        for (int k = 0; k < 16; k++) s += sred[k * SRED_STR + v];
        const int b = v >> 4;
        const int d = v & 15;
        g_part[(kp * BATCH + b) * 512 + o * 16 + d] = s;
    }
}

// ============================================================================
// Finalize: sum 4 kp partials + squash.  grid 64 (b), 512 threads (o*16+d).
// ============================================================================
__global__ void __launch_bounds__(512)
caps_fin(float* __restrict__ out) {
    __shared__ float q[512];
    const int b  = blockIdx.x;
    const int od = threadIdx.x;
    float s = 0.f;
#pragma unroll
    for (int kp = 0; kp < 4; kp++) s += g_part[(kp * BATCH + b) * 512 + od];
    q[od] = s * s;
    __syncthreads();
    const int o = od >> 4;
    float s2 = 0.f;
#pragma unroll
    for (int k = 0; k < 16; k++) s2 += q[o * 16 + k];
    const float scale = s2 / ((1.f + s2) * sqrtf(s2 + 1e-7f));
    out[(size_t)b * 512 + od] = scale * s;
}

// ============================================================================
extern "C" void kernel_launch(void* const* d_in, const int* in_sizes, int n_in,
                              void* d_out, int out_size) {
    const float* inp;
    const float* Wg;
    if (in_sizes[0] == BATCH * NI * DI) {
        inp = (const float*)d_in[0];
        Wg  = (const float*)d_in[1];
    } else {
        inp = (const float*)d_in[1];
        Wg  = (const float*)d_in[0];
    }

    cudaFuncSetAttribute(caps_contract, cudaFuncAttributeMaxDynamicSharedMemorySize,
                         SMEMC_BYTES);

    caps_route<<<NI, 512>>>(inp, Wg);
    caps_contract<<<dim3(KP, NO), 512, SMEMC_BYTES>>>(inp, Wg);
    caps_fin<<<BATCH, 512>>>((float*)d_out);
}

// round 10
// speedup vs baseline: 3.5255x; 1.1743x over previous
#include <cuda_runtime.h>
#include <cstdint>

#define BATCH 64
#define NI    2048
#define DI    16
#define NO    32
#define DOUT  16

#define KP    4
#define NPB   (NI / KP)     // 512 n per block
#define NPW   (NPB / 16)    // 32 n per warp

__device__ float g_wsum[NI * NO * DI];            // 4 MB  [n][o][i]
__device__ float g_c2[(size_t)NO * NI * BATCH];   // 16 MB [o][n][b]
__device__ float g_part[KP * BATCH * 512];        // [kp][b][o*16+d]

// ---------------------------------------------------------------------------
__device__ __forceinline__ float tf32r(float v) {
    unsigned r; asm("cvt.rna.tf32.f32 %0, %1;" : "=r"(r) : "f"(v));
    return __uint_as_float(r);
}
__device__ __forceinline__ void mma8(float* d,
                                     float a0, float a1, float a2, float a3,
                                     float b0, float b1) {
    asm volatile(
        "mma.sync.aligned.m16n8k8.row.col.f32.tf32.tf32.f32 "
        "{%0,%1,%2,%3}, {%4,%5,%6,%7}, {%8,%9}, {%0,%1,%2,%3};"
        : "+f"(d[0]), "+f"(d[1]), "+f"(d[2]), "+f"(d[3])
        : "r"(__float_as_uint(a0)), "r"(__float_as_uint(a1)),
          "r"(__float_as_uint(a2)), "r"(__float_as_uint(a3)),
          "r"(__float_as_uint(b0)), "r"(__float_as_uint(b1)));
}

// ============================================================================
// K0: Wsum[n][o][i] = sum_d W[n][o][d][i].  (R2 kernel, measured 13.8 us)
// ============================================================================
__global__ void __launch_bounds__(256)
caps_wsum(const float* __restrict__ Wg) {
    int flat = blockIdx.x * 256 + threadIdx.x;      // (n*32 + o)*4 + iq
    int iq = flat & 3;
    int no = flat >> 2;
    const float4* src = (const float4*)(Wg + (size_t)no * 256 + iq * 4);
    float4 s = make_float4(0.f, 0.f, 0.f, 0.f);
#pragma unroll
    for (int d = 0; d < 16; d++) {
        float4 v = __ldg(src + d * 4);
        s.x += v.x; s.y += v.y; s.z += v.z; s.w += v.w;
    }
    *(float4*)(g_wsum + (size_t)no * 16 + iq * 4) = s;
}

// ============================================================================
// K1: routing from Wsum.  grid 1024, block 128 (4 warps).
//   Warp = (nn = wid>>1, bh = wid&1); n = 2*blk + nn; lane = b - bh*32.
//   lane-=b / serial-o organization: softmax reductions are register adds,
//   no shfl chains; one rcp per softmax.
// ============================================================================
__global__ void __launch_bounds__(128)
caps_route2(const float* __restrict__ inp) {
    __shared__ float ws[2][512];     // [nn][o*16+i]
    const int t  = threadIdx.x;
    const int n2 = blockIdx.x;

    // load Wsum for both n (coalesced float4)
#pragma unroll
    for (int k = 0; k < 2; k++) {
        const int f   = t + k * 128;       // float4 idx 0..255
        const int nn2 = f >> 7;
        const int rem = f & 127;
        *(float4*)(&ws[nn2][rem * 4]) =
            *(const float4*)(g_wsum + ((size_t)(2 * n2 + nn2)) * 512 + rem * 4);
    }
    __syncthreads();

    const int wid  = t >> 5;
    const int lane = t & 31;
    const int nn   = wid >> 1;
    const int bh   = wid & 1;
    const int n    = 2 * n2 + nn;
    const int b    = bh * 32 + lane;

    // x[b][n][0..15]
    const float4* xr = (const float4*)(inp + ((size_t)b * NI + n) * 16);
    const float4 x0 = __ldg(xr + 0), x1 = __ldg(xr + 1);
    const float4 x2 = __ldg(xr + 2), x3 = __ldg(xr + 3);

    // h[o] = ws[o] . x   (ws broadcast LDS)
    float h[32];
#pragma unroll
    for (int o = 0; o < 32; o++) {
        const float4* wr = (const float4*)(&ws[nn][o * 16]);
        float4 w0 = wr[0], w1 = wr[1], w2 = wr[2], w3 = wr[3];
        float hv = w0.x * x0.x;
        hv = fmaf(w0.y, x0.y, hv); hv = fmaf(w0.z, x0.z, hv); hv = fmaf(w0.w, x0.w, hv);
        hv = fmaf(w1.x, x1.x, hv); hv = fmaf(w1.y, x1.y, hv); hv = fmaf(w1.z, x1.z, hv); hv = fmaf(w1.w, x1.w, hv);
        hv = fmaf(w2.x, x2.x, hv); hv = fmaf(w2.y, x2.y, hv); hv = fmaf(w2.z, x2.z, hv); hv = fmaf(w2.w, x2.w, hv);
        hv = fmaf(w3.x, x3.x, hv); hv = fmaf(w3.y, x3.y, hv); hv = fmaf(w3.z, x3.z, hv); hv = fmaf(w3.w, x3.w, hv);
        h[o] = hv;
    }

    // softmax chain (no-max: |b1| <= ~1, |b2| <= ~6 -> exp safe)
    float e1[32], s1 = 0.f;
#pragma unroll
    for (int o = 0; o < 32; o++) {
        e1[o] = __expf(h[o] * 0.03125f);
        s1 += e1[o];
    }
    const float inv1 = __fdividef(1.f, s1);
    float e2[32], s2 = 0.f;
#pragma unroll
    for (int o = 0; o < 32; o++) {
        const float b1 = h[o] * 0.03125f;
        const float b2 = fmaf(e1[o] * inv1, h[o], b1);
        e2[o] = __expf(b2);
        s2 += e2[o];
    }
    const float inv2 = __fdividef(1.f, s2);

    // store c2[o][n][b] (coalesced per o)
#pragma unroll
    for (int o = 0; o < 32; o++)
        g_c2[((size_t)o * NI + n) * BATCH + b] = e2[o] * inv2;
}

// ============================================================================
// K3: mma.sync tf32 contraction.  grid (4 kp, 32 o), 512 threads = 16 warps.
//   Warp w: n = n0 + w + 16*j; full M=64 x N=16, 3xTF32, 32 acc regs.
//   All gmem loads for an iteration hoisted to the top (MLP batching).
// ============================================================================
#define SRED_STR 1032
#define SMEMC_BYTES (16 * SRED_STR * 4)   // 66048

__global__ __launch_bounds__(512, 1)
void caps_contract(const float* __restrict__ inp, const float* __restrict__ Wg) {
    extern __shared__ float sred[];
    const int t    = threadIdx.x;
    const int w    = t >> 5;
    const int lane = t & 31;
    const int r    = lane >> 2;
    const int c    = lane & 3;
    const int kp   = blockIdx.x;
    const int o    = blockIdx.y;
    const int n0   = kp * NPB;

    float acc[4][2][4];
#pragma unroll
    for (int mt = 0; mt < 4; mt++)
#pragma unroll
        for (int dt = 0; dt < 2; dt++)
#pragma unroll
            for (int q = 0; q < 4; q++) acc[mt][dt][q] = 0.f;

    const float* xb  = inp + (size_t)r * (NI * DI) + 4 * c;
    const float* c2p = g_c2 + (size_t)o * (NI * BATCH) + r;
    const float* wbp = Wg + (size_t)o * 256 + r * 16 + c * 4;

    for (int j = 0; j < NPW; j++) {
        const int n = n0 + w + j * 16;
        const float* c2n = c2p + (size_t)n * BATCH;
        const float* xn  = xb + (size_t)n * DI;

        // ---- hoisted loads: 2 W + 8 x + 8 c2 ----
        float4 wv0 = __ldg((const float4*)(wbp + (size_t)n * 8192));
        float4 wv1 = __ldg((const float4*)(wbp + (size_t)n * 8192 + 128));
        float4 xv[8];
        float  cva[8];
#pragma unroll
        for (int mt = 0; mt < 4; mt++) {
            cva[2 * mt]     = __ldg(c2n + mt * 16);
            cva[2 * mt + 1] = __ldg(c2n + mt * 16 + 8);
            xv[2 * mt]      = __ldg((const float4*)(xn + (size_t)(mt * 16) * (NI * DI)));
            xv[2 * mt + 1]  = __ldg((const float4*)(xn + (size_t)(mt * 16 + 8) * (NI * DI)));
        }

        // ---- B fragments hi/lo ----
        float bh[2][2][2], bl[2][2][2];    // [dt][g][slot]
        bh[0][0][0] = tf32r(wv0.x);  bl[0][0][0] = wv0.x - bh[0][0][0];
        bh[0][0][1] = tf32r(wv0.y);  bl[0][0][1] = wv0.y - bh[0][0][1];
        bh[0][1][0] = tf32r(wv0.z);  bl[0][1][0] = wv0.z - bh[0][1][0];
        bh[0][1][1] = tf32r(wv0.w);  bl[0][1][1] = wv0.w - bh[0][1][1];
        bh[1][0][0] = tf32r(wv1.x);  bl[1][0][0] = wv1.x - bh[1][0][0];
        bh[1][0][1] = tf32r(wv1.y);  bl[1][0][1] = wv1.y - bh[1][0][1];
        bh[1][1][0] = tf32r(wv1.z);  bl[1][1][0] = wv1.z - bh[1][1][0];
        bh[1][1][1] = tf32r(wv1.w);  bl[1][1][1] = wv1.w - bh[1][1][1];

#pragma unroll
        for (int mt = 0; mt < 4; mt++) {
            const float c2a = cva[2 * mt];
            const float c2b = cva[2 * mt + 1];
            const float x0e[4] = {xv[2*mt].x, xv[2*mt].y, xv[2*mt].z, xv[2*mt].w};
            const float x1e[4] = {xv[2*mt+1].x, xv[2*mt+1].y, xv[2*mt+1].z, xv[2*mt+1].w};
#pragma unroll
            for (int g = 0; g < 2; g++) {
                const float y0 = c2a * x0e[2 * g];
                const float y2 = c2a * x0e[2 * g + 1];
                const float y1 = c2b * x1e[2 * g];
                const float y3 = c2b * x1e[2 * g + 1];
                const float aH0 = tf32r(y0), aH1 = tf32r(y1);
                const float aH2 = tf32r(y2), aH3 = tf32r(y3);
                const float aL0 = y0 - aH0, aL1 = y1 - aH1;
                const float aL2 = y2 - aH2, aL3 = y3 - aH3;
#pragma unroll
                for (int dt = 0; dt < 2; dt++) {
                    mma8(acc[mt][dt], aH0, aH1, aH2, aH3, bh[dt][g][0], bh[dt][g][1]);
                    mma8(acc[mt][dt], aH0, aH1, aH2, aH3, bl[dt][g][0], bl[dt][g][1]);
                    mma8(acc[mt][dt], aL0, aL1, aL2, aL3, bh[dt][g][0], bh[dt][g][1]);
                }
            }
        }
    }

    // ---- epilogue: per-warp partial -> smem, cross-warp reduce -------------
#pragma unroll
    for (int mt = 0; mt < 4; mt++)
#pragma unroll
        for (int dt = 0; dt < 2; dt++) {
            const int base0 = w * SRED_STR + (mt * 16 + r) * 16 + dt * 8 + 2 * c;
            *(float2*)(sred + base0)       = make_float2(acc[mt][dt][0], acc[mt][dt][1]);
            *(float2*)(sred + base0 + 128) = make_float2(acc[mt][dt][2], acc[mt][dt][3]);
        }
    __syncthreads();

#pragma unroll
    for (int rep = 0; rep < 2; rep++) {
        const int v = t + rep * 512;
        float s = 0.f;
#pragma unroll
        for (int k = 0; k < 16; k++) s += sred[k * SRED_STR + v];
        const int b = v >> 4;
        const int d = v & 15;
        g_part[(kp * BATCH + b) * 512 + o * 16 + d] = s;
    }
}

// ============================================================================
// Finalize: sum 4 kp partials + squash.  grid 64 (b), 512 threads (o*16+d).
// ============================================================================
__global__ void __launch_bounds__(512)
caps_fin(float* __restrict__ out) {
    __shared__ float q[512];
    const int b  = blockIdx.x;
    const int od = threadIdx.x;
    float s = 0.f;
#pragma unroll
    for (int kp = 0; kp < 4; kp++) s += g_part[(kp * BATCH + b) * 512 + od];
    q[od] = s * s;
    __syncthreads();
    const int o = od >> 4;
    float s2 = 0.f;
#pragma unroll
    for (int k = 0; k < 16; k++) s2 += q[o * 16 + k];
    const float scale = s2 / ((1.f + s2) * sqrtf(s2 + 1e-7f));
    out[(size_t)b * 512 + od] = scale * s;
}

// ============================================================================
extern "C" void kernel_launch(void* const* d_in, const int* in_sizes, int n_in,
                              void* d_out, int out_size) {
    const float* inp;
    const float* Wg;
    if (in_sizes[0] == BATCH * NI * DI) {
        inp = (const float*)d_in[0];
        Wg  = (const float*)d_in[1];
    } else {
        inp = (const float*)d_in[1];
        Wg  = (const float*)d_in[0];
    }

    cudaFuncSetAttribute(caps_contract, cudaFuncAttributeMaxDynamicSharedMemorySize,
                         SMEMC_BYTES);

    caps_wsum<<<1024, 256>>>(Wg);
    caps_route2<<<NI / 2, 128>>>(inp);
    caps_contract<<<dim3(KP, NO), 512, SMEMC_BYTES>>>(inp, Wg);
    caps_fin<<<BATCH, 512>>>((float*)d_out);
}